// round 1
// baseline (speedup 1.0000x reference)
#include <cuda_runtime.h>
#include <math.h>

#define CC 96
#define HH 256
#define WWID 256
#define HW 65536
#define BATCH 4
#define NTOK 64
#define NHEADS 6
#define HD 16
#define NWIN 1024
#define BWIN 4096
#define NC 6144
#define HIDDEN 256
#define PD 30

// ---------------- scratch (device globals; no allocations allowed) ----------------
__device__ float g_V[BATCH * CC * HW];          // 1x1 conv V output, NCHW
__device__ float g_QK[BATCH * 2 * CC * HW];     // 1x1 conv QK output, NCHW
__device__ float g_aw[(size_t)BWIN * NC];       // window-attn output: [win][n*C+c]
__device__ float g_hidden[BWIN * HIDDEN];       // relu(xg @ pe_w1^T + b1)
__device__ float g_emb[BWIN * PD];              // l2-normalized patch embeddings
__device__ float g_attg[(size_t)BATCH * NWIN * NWIN];
__device__ float g_rw[(size_t)BWIN * NC];
__device__ float g_attn_out[BATCH * CC * HW];   // window-reversed, renormalized
__device__ float g_conv[BATCH * CC * HW];       // depthwise conv output
__device__ float g_bias[NHEADS * NTOK * NTOK];  // rel-pos MLP bias [h][n][m]
__device__ double g_acc[BATCH][2];              // src sum / sumsq accumulators
__device__ float g_stats[BATCH][4];             // srcmean, srcstd, curmean, curstd

// ---------------- small helpers ----------------
__global__ void zero_acc_kernel() {
    int i = threadIdx.x;
    if (i < BATCH) { g_acc[i][0] = 0.0; g_acc[i][1] = 0.0; }
}

// relative-position bias MLP: bias[h][n][m]
__global__ void bias_kernel(const float* __restrict__ w1, const float* __restrict__ b1,
                            const float* __restrict__ w2, const float* __restrict__ b2) {
    int n = blockIdx.x;     // 0..63
    int m = threadIdx.x;    // 0..63
    float d0 = (float)((n >> 3) - (m >> 3));
    float d1 = (float)((n & 7) - (m & 7));
    float r0 = copysignf(log1pf(fabsf(d0)), d0);
    float r1 = copysignf(log1pf(fabsf(d1)), d1);
    float out[NHEADS];
#pragma unroll
    for (int h = 0; h < NHEADS; h++) out[h] = b2[h];
    for (int k = 0; k < 256; k++) {
        float hv = fmaxf(w1[2 * k] * r0 + w1[2 * k + 1] * r1 + b1[k], 0.f);
#pragma unroll
        for (int h = 0; h < NHEADS; h++) out[h] += w2[h * 256 + k] * hv;
    }
#pragma unroll
    for (int h = 0; h < NHEADS; h++) g_bias[(h * NTOK + n) * NTOK + m] = out[h];
}

// ---------------- generic 128x128x8 SIMT fp32 GEMM ----------------
// C[m][n] = sum_k A[m][k] * Bop[k][n]   (Bop = B (K,N) row-major, or B^T with B (N,K) when BT)
// epilogues: +bias (per-M or per-N), relu, B2 added to B operand (for conv+attn fuse)
template <bool BT, bool BIAS_N, bool RELU, bool ADD2>
__global__ __launch_bounds__(256) void gemm_kernel(
    const float* __restrict__ A, const float* __restrict__ B,
    const float* __restrict__ B2, const float* __restrict__ bias,
    float* __restrict__ C, int M, int N, int K,
    long long sA, long long sB, long long sC) {
    int bz = blockIdx.z;
    A += bz * sA; B += bz * sB; C += bz * sC;
    if (ADD2) B2 += bz * sB;
    __shared__ float As[8][128];
    __shared__ float Bs[8][128];
    int tid = threadIdx.x;
    int m0 = blockIdx.y * 128, n0 = blockIdx.x * 128;
    int trow = (tid >> 4) << 3;
    int tcol = (tid & 15) << 3;
    float acc[8][8];
#pragma unroll
    for (int i = 0; i < 8; i++)
#pragma unroll
        for (int j = 0; j < 8; j++) acc[i][j] = 0.f;

    for (int k0 = 0; k0 < K; k0 += 8) {
#pragma unroll
        for (int i = 0; i < 4; i++) {
            int idx = tid + i * 256;
            int m = idx >> 3, kk = idx & 7;
            As[kk][m] = (m0 + m < M) ? A[(long long)(m0 + m) * K + k0 + kk] : 0.f;
        }
#pragma unroll
        for (int i = 0; i < 4; i++) {
            int idx = tid + i * 256;
            if (BT) {
                int n = idx >> 3, kk = idx & 7;
                Bs[kk][n] = (n0 + n < N) ? B[(long long)(n0 + n) * K + k0 + kk] : 0.f;
            } else {
                int kk = idx >> 7, n = idx & 127;
                float v = 0.f;
                if (n0 + n < N) {
                    long long o = (long long)(k0 + kk) * N + n0 + n;
                    v = B[o];
                    if (ADD2) v += B2[o];
                }
                Bs[kk][n] = v;
            }
        }
        __syncthreads();
#pragma unroll
        for (int kk = 0; kk < 8; kk++) {
            float a[8], bb[8];
#pragma unroll
            for (int i = 0; i < 8; i++) a[i] = As[kk][trow + i];
#pragma unroll
            for (int j = 0; j < 8; j++) bb[j] = Bs[kk][tcol + j];
#pragma unroll
            for (int i = 0; i < 8; i++)
#pragma unroll
                for (int j = 0; j < 8; j++) acc[i][j] += a[i] * bb[j];
        }
        __syncthreads();
    }
#pragma unroll
    for (int i = 0; i < 8; i++) {
        int m = m0 + trow + i;
        if (m >= M) continue;
        float bm = (!BIAS_N && bias != nullptr) ? bias[m] : 0.f;
#pragma unroll
        for (int j = 0; j < 8; j++) {
            int n = n0 + tcol + j;
            if (n >= N) continue;
            float v = acc[i][j] + bm;
            if (BIAS_N) v += bias[n];
            if (RELU) v = fmaxf(v, 0.f);
            C[(long long)m * N + n] = v;
        }
    }
}

// ---------------- window attention: one block per (window, head) ----------------
__global__ __launch_bounds__(128) void attn_kernel() {
    int win = blockIdx.x, h = blockIdx.y;
    int b = win >> 10;
    int wl = win & 1023;
    int wy = wl >> 5, wx = wl & 31;
    int y0 = wy * 8, x0 = wx * 8;
    __shared__ float qs[NTOK][HD + 1];
    __shared__ float ks[NTOK][HD + 1];
    __shared__ float vs[NTOK][HD + 1];
    __shared__ float at[NTOK][NTOK + 1];
    int tid = threadIdx.x;
    const float scale = 0.25f;  // hd^-0.5
    const float* Qb = g_QK + ((long long)b * 2 * CC + h * HD) * HW;
    const float* Kb = g_QK + ((long long)b * 2 * CC + CC + h * HD) * HW;
    const float* Vb = g_V + ((long long)b * CC + h * HD) * HW;
    for (int idx = tid; idx < NTOK * HD; idx += 128) {
        int ix = idx & 7, iy = (idx >> 3) & 7, d = idx >> 6;
        long long off = (long long)d * HW + (y0 + iy) * WWID + x0 + ix;
        int t = iy * 8 + ix;
        qs[t][d] = Qb[off] * scale;
        ks[t][d] = Kb[off];
        vs[t][d] = Vb[off];
    }
    __syncthreads();
    // scores + bias
    {
        int m = tid & 63;
        float kreg[HD];
#pragma unroll
        for (int d = 0; d < HD; d++) kreg[d] = ks[m][d];
        for (int i = 0; i < 32; i++) {
            int n = (i * 128 + tid) >> 6;
            float s = 0.f;
#pragma unroll
            for (int d = 0; d < HD; d++) s += qs[n][d] * kreg[d];
            at[n][m] = s + g_bias[(h * NTOK + n) * NTOK + m];
        }
    }
    __syncthreads();
    // softmax per row
    if (tid < NTOK) {
        int n = tid;
        float mx = -1e30f;
        for (int j = 0; j < NTOK; j++) mx = fmaxf(mx, at[n][j]);
        float sum = 0.f;
        for (int j = 0; j < NTOK; j++) { float e = expf(at[n][j] - mx); at[n][j] = e; sum += e; }
        float inv = 1.f / sum;
        for (int j = 0; j < NTOK; j++) at[n][j] *= inv;
    }
    __syncthreads();
    // out = attn @ v
    {
        int d = tid & 15;
        int g = tid >> 4;  // 0..7
        float acc[8];
#pragma unroll
        for (int j = 0; j < 8; j++) acc[j] = 0.f;
        for (int mm = 0; mm < NTOK; mm++) {
            float v = vs[mm][d];
#pragma unroll
            for (int j = 0; j < 8; j++) acc[j] += at[g + j * 8][mm] * v;
        }
        float* awp = g_aw + (long long)win * NC + h * HD + d;
#pragma unroll
        for (int j = 0; j < 8; j++) awp[(g + j * 8) * CC] = acc[j];
    }
}

// ---------------- src stats (sum/sumsq of aw per batch) ----------------
__global__ __launch_bounds__(256) void stats_src_kernel() {
    int b = blockIdx.y;
    const float* p = g_aw + (long long)b * NWIN * NC;
    long long n = (long long)NWIN * NC;
    double s = 0.0, s2 = 0.0;
    for (long long i = (long long)blockIdx.x * blockDim.x + threadIdx.x; i < n;
         i += (long long)gridDim.x * blockDim.x) {
        double v = p[i];
        s += v; s2 += v * v;
    }
    __shared__ double sh[256], sh2[256];
    sh[threadIdx.x] = s; sh2[threadIdx.x] = s2;
    __syncthreads();
    for (int st = 128; st > 0; st >>= 1) {
        if (threadIdx.x < st) { sh[threadIdx.x] += sh[threadIdx.x + st]; sh2[threadIdx.x] += sh2[threadIdx.x + st]; }
        __syncthreads();
    }
    if (threadIdx.x == 0) { atomicAdd(&g_acc[b][0], sh[0]); atomicAdd(&g_acc[b][1], sh2[0]); }
}

// ---------------- emb second layer + l2norm ----------------
__global__ __launch_bounds__(256) void emb2_kernel(const float* __restrict__ w2,
                                                   const float* __restrict__ b2) {
    int w = blockIdx.x;
    __shared__ float h[HIDDEN];
    __shared__ float e[PD];
    __shared__ float nrm;
    int tid = threadIdx.x;
    h[tid] = g_hidden[w * HIDDEN + tid];
    __syncthreads();
    if (tid < PD) {
        float a = b2[tid];
        const float* wr = w2 + tid * HIDDEN;
        for (int j = 0; j < HIDDEN; j++) a += wr[j] * h[j];
        e[tid] = a;
    }
    __syncthreads();
    if (tid == 0) {
        float s = 0.f;
        for (int i = 0; i < PD; i++) s += e[i] * e[i];
        nrm = 1.f / (sqrtf(s) + 1e-8f);
    }
    __syncthreads();
    if (tid < PD) g_emb[w * PD + tid] = e[tid] * nrm;
}

// ---------------- finalize stats: cur (over emb) + src (from accumulators) ----------------
__global__ __launch_bounds__(256) void stats2_kernel() {
    int b = blockIdx.x;
    const float* p = g_emb + b * NWIN * PD;
    int n = NWIN * PD;
    double s = 0.0, s2 = 0.0;
    for (int i = threadIdx.x; i < n; i += 256) { double v = p[i]; s += v; s2 += v * v; }
    __shared__ double sh[256], sh2[256];
    sh[threadIdx.x] = s; sh2[threadIdx.x] = s2;
    __syncthreads();
    for (int st = 128; st > 0; st >>= 1) {
        if (threadIdx.x < st) { sh[threadIdx.x] += sh[threadIdx.x + st]; sh2[threadIdx.x] += sh2[threadIdx.x + st]; }
        __syncthreads();
    }
    if (threadIdx.x == 0) {
        double mean = sh[0] / n;
        double var = sh2[0] / n - mean * mean;
        g_stats[b][2] = (float)mean;
        g_stats[b][3] = (float)sqrt(var + 1e-8);
        double cnt = (double)NWIN * NC;
        double sm = g_acc[b][0] / cnt;
        double sv = g_acc[b][1] / cnt - sm * sm;
        g_stats[b][0] = (float)sm;
        g_stats[b][1] = (float)sqrt(sv + 1e-8);
    }
}

// ---------------- global attention weights ----------------
__global__ __launch_bounds__(256) void attg_kernel(const float* __restrict__ alpha,
                                                   const float* __restrict__ beta) {
    int b = blockIdx.y, n = blockIdx.x;
    __shared__ float en[PD];
    __shared__ float row[NWIN];
    __shared__ float red[256];
    int tid = threadIdx.x;
    if (tid < PD) en[tid] = g_emb[(b * NWIN + n) * PD + tid];
    __syncthreads();
    float al = 30.f * alpha[0], be = 20.f * beta[0];
    float ls = 0.f;
    for (int m = tid; m < NWIN; m += 256) {
        const float* em = g_emb + (b * NWIN + m) * PD;
        float s = 0.f;
#pragma unroll
        for (int d = 0; d < PD; d++) s += en[d] * em[d];
        float v = expf(al * s + be);
        row[m] = v; ls += v;
    }
    red[tid] = ls;
    __syncthreads();
    for (int st = 128; st > 0; st >>= 1) {
        if (tid < st) red[tid] += red[tid + st];
        __syncthreads();
    }
    float inv = 1.f / (red[0] + 1e-8f);
    float* outp = g_attg + ((long long)b * NWIN + n) * NWIN;
    for (int m = tid; m < NWIN; m += 256) outp[m] = row[m] * inv;
}

// ---------------- renormalize rw + window reverse (NCHW) ----------------
__global__ __launch_bounds__(256) void norm_rev_kernel() {
    int win = blockIdx.x;
    int b = win >> 10, wl = win & 1023, wy = wl >> 5, wx = wl & 31;
    __shared__ float s[CC * 65];
    int tid = threadIdx.x;
    float cm = g_stats[b][2], cs = g_stats[b][3], sm0 = g_stats[b][0], ss = g_stats[b][1];
    float sc = ss / cs;
    float off = sm0 - cm * sc;
    const float* p = g_rw + (long long)win * NC;
    for (int i = tid; i < NC; i += 256) {
        int n = i / CC, c = i - n * CC;
        s[c * 65 + n] = p[i] * sc + off;
    }
    __syncthreads();
    float* outp = g_attn_out + (long long)b * CC * HW + (wy * 8) * WWID + wx * 8;
    for (int t = tid; t < CC * 8; t += 256) {
        int c = t >> 3, iy = t & 7;
        float* o = outp + (long long)c * HW + iy * WWID;
        const float* sr = &s[c * 65];
#pragma unroll
        for (int ix = 0; ix < 8; ix++) o[ix] = sr[iy * 8 + ix];
    }
}

// ---------------- depthwise 5x5 conv on V (reflect pad) ----------------
__global__ __launch_bounds__(256) void dwconv_kernel(const float* __restrict__ dw_w,
                                                     const float* __restrict__ dw_b) {
    int bc = blockIdx.z;
    int c = bc % CC;
    __shared__ float wgt[25];
    if (threadIdx.y == 0 && threadIdx.x < 25) wgt[threadIdx.x] = dw_w[c * 25 + threadIdx.x];
    __syncthreads();
    int x = blockIdx.x * 32 + threadIdx.x;
    int y = blockIdx.y * 8 + threadIdx.y;
    const float* vp = g_V + (long long)bc * HW;
    float acc = dw_b[c];
#pragma unroll
    for (int ky = 0; ky < 5; ky++) {
        int yy = y + ky - 2;
        yy = yy < 0 ? -yy : (yy > 255 ? 510 - yy : yy);
#pragma unroll
        for (int kx = 0; kx < 5; kx++) {
            int xx = x + kx - 2;
            xx = xx < 0 ? -xx : (xx > 255 ? 510 - xx : xx);
            acc += wgt[ky * 5 + kx] * vp[yy * WWID + xx];
        }
    }
    g_conv[(long long)bc * HW + y * WWID + x] = acc;
}

// ---------------- launch ----------------
extern "C" void kernel_launch(void* const* d_in, const int* in_sizes, int n_in,
                              void* d_out, int out_size) {
    (void)in_sizes; (void)n_in; (void)out_size;
    const float* X        = (const float*)d_in[0];
    const float* V_w      = (const float*)d_in[1];
    const float* V_b      = (const float*)d_in[2];
    const float* QK_w     = (const float*)d_in[3];
    const float* QK_b     = (const float*)d_in[4];
    const float* proj_w   = (const float*)d_in[5];
    const float* proj_b   = (const float*)d_in[6];
    const float* dw_w     = (const float*)d_in[7];
    const float* dw_b     = (const float*)d_in[8];
    const float* meta_w1  = (const float*)d_in[9];
    const float* meta_b1  = (const float*)d_in[10];
    const float* meta_w2  = (const float*)d_in[11];
    const float* meta_b2  = (const float*)d_in[12];
    const float* pe_w1    = (const float*)d_in[13];
    const float* pe_b1    = (const float*)d_in[14];
    const float* pe_w2    = (const float*)d_in[15];
    const float* pe_b2    = (const float*)d_in[16];
    const float* att_alpha = (const float*)d_in[17];
    const float* att_beta  = (const float*)d_in[18];
    float* out = (float*)d_out;

    float *pV, *pQK, *paw, *phid, *pattg, *prw, *pao, *pconv;
    cudaGetSymbolAddress((void**)&pV, g_V);
    cudaGetSymbolAddress((void**)&pQK, g_QK);
    cudaGetSymbolAddress((void**)&paw, g_aw);
    cudaGetSymbolAddress((void**)&phid, g_hidden);
    cudaGetSymbolAddress((void**)&pattg, g_attg);
    cudaGetSymbolAddress((void**)&prw, g_rw);
    cudaGetSymbolAddress((void**)&pao, g_attn_out);
    cudaGetSymbolAddress((void**)&pconv, g_conv);

    zero_acc_kernel<<<1, 32>>>();
    bias_kernel<<<64, 64>>>(meta_w1, meta_b1, meta_w2, meta_b2);

    // QK = QK_w @ X   (M=192, N=65536, K=96) per batch
    gemm_kernel<false, false, false, false><<<dim3(512, 2, BATCH), 256>>>(
        QK_w, X, nullptr, QK_b, pQK, 2 * CC, HW, CC,
        0LL, (long long)CC * HW, (long long)2 * CC * HW);
    // V = V_w @ X
    gemm_kernel<false, false, false, false><<<dim3(512, 1, BATCH), 256>>>(
        V_w, X, nullptr, V_b, pV, CC, HW, CC,
        0LL, (long long)CC * HW, (long long)CC * HW);

    attn_kernel<<<dim3(BWIN, NHEADS), 128>>>();
    stats_src_kernel<<<dim3(64, BATCH), 256>>>();

    // hidden = relu(aw @ pe_w1^T + pe_b1)   (M=4096, N=256, K=6144)
    gemm_kernel<true, true, true, false><<<dim3(2, 32, 1), 256>>>(
        paw, pe_w1, nullptr, pe_b1, phid, BWIN, HIDDEN, NC, 0LL, 0LL, 0LL);
    emb2_kernel<<<BWIN, 256>>>(pe_w2, pe_b2);
    stats2_kernel<<<BATCH, 256>>>();
    attg_kernel<<<dim3(NWIN, BATCH), 256>>>(att_alpha, att_beta);

    // rw = att_g @ aw   (M=1024, N=6144, K=1024) per batch
    gemm_kernel<false, false, false, false><<<dim3(48, 8, BATCH), 256>>>(
        pattg, paw, nullptr, nullptr, prw, NWIN, NC, NWIN,
        (long long)NWIN * NWIN, (long long)NWIN * NC, (long long)NWIN * NC);

    norm_rev_kernel<<<BWIN, 256>>>();
    dwconv_kernel<<<dim3(8, 32, BATCH * CC), dim3(32, 8)>>>(dw_w, dw_b);

    // out = proj_w @ (conv + attn_out) + proj_b   (M=96, N=65536, K=96) per batch
    gemm_kernel<false, false, false, true><<<dim3(512, 1, BATCH), 256>>>(
        proj_w, pconv, pao, proj_b, out, CC, HW, CC,
        0LL, (long long)CC * HW, (long long)CC * HW);
}

// round 2
// speedup vs baseline: 2.2377x; 2.2377x over previous
#include <cuda_runtime.h>
#include <math.h>
#include <stdint.h>

#define CC 96
#define HH 256
#define WWID 256
#define HW 65536
#define BATCH 4
#define NTOK 64
#define NHEADS 6
#define HD 16
#define NWIN 1024
#define BWIN 4096
#define NC 6144
#define HIDDEN 256
#define PD 30
#define KSPLIT 4

// ---------------- scratch (device globals; no allocations allowed) ----------------
__device__ float g_V[BATCH * CC * HW];
__device__ float g_QK[BATCH * 2 * CC * HW];
__device__ float g_aw[(size_t)BWIN * NC];
__device__ float g_hidden[(size_t)KSPLIT * BWIN * HIDDEN];  // split-K partials
__device__ float g_emb[BWIN * PD];
__device__ float g_attg[(size_t)BATCH * NWIN * NWIN];
__device__ float g_rw[(size_t)BWIN * NC];
__device__ float g_attn_out[BATCH * CC * HW];
__device__ float g_conv[BATCH * CC * HW];
__device__ float g_bias[NHEADS * NTOK * NTOK];
__device__ double g_acc[BATCH][2];
__device__ float g_stats[BATCH][4];

__global__ void zero_acc_kernel() {
    int i = threadIdx.x;
    if (i < BATCH) { g_acc[i][0] = 0.0; g_acc[i][1] = 0.0; }
}

// relative-position bias MLP
__global__ void bias_kernel(const float* __restrict__ w1, const float* __restrict__ b1,
                            const float* __restrict__ w2, const float* __restrict__ b2) {
    int n = blockIdx.x, m = threadIdx.x;
    float d0 = (float)((n >> 3) - (m >> 3));
    float d1 = (float)((n & 7) - (m & 7));
    float r0 = copysignf(log1pf(fabsf(d0)), d0);
    float r1 = copysignf(log1pf(fabsf(d1)), d1);
    float out[NHEADS];
#pragma unroll
    for (int h = 0; h < NHEADS; h++) out[h] = b2[h];
    for (int k = 0; k < 256; k++) {
        float hv = fmaxf(w1[2 * k] * r0 + w1[2 * k + 1] * r1 + b1[k], 0.f);
#pragma unroll
        for (int h = 0; h < NHEADS; h++) out[h] += w2[h * 256 + k] * hv;
    }
#pragma unroll
    for (int h = 0; h < NHEADS; h++) g_bias[(h * NTOK + n) * NTOK + m] = out[h];
}

// ---------------- TF32 tensor-core GEMM: 128x128x16 tile, 8 warps ----------------
__device__ __forceinline__ uint32_t f2tf(float f) {
    uint32_t u;
    asm("cvt.rna.tf32.f32 %0, %1;" : "=r"(u) : "f"(f));
    return u;
}
__device__ __forceinline__ void mma_tf32(float d[4], const uint32_t a[4],
                                         const uint32_t b[2]) {
    asm volatile(
        "mma.sync.aligned.m16n8k8.row.col.f32.tf32.tf32.f32 "
        "{%0,%1,%2,%3}, {%4,%5,%6,%7}, {%8,%9}, {%0,%1,%2,%3};\n"
        : "+f"(d[0]), "+f"(d[1]), "+f"(d[2]), "+f"(d[3])
        : "r"(a[0]), "r"(a[1]), "r"(a[2]), "r"(a[3]), "r"(b[0]), "r"(b[1]));
}

// C[m][n] = sum_k A[m][k]*Bop[k][n];  Bop = B[K,N] (NN) or B[N,K]^T (BT).
// SPLITK: gridDim.z indexes K-chunks of size sA; C += bz*sC (partial buffers).
template <bool BT, bool BIAS_N, bool RELU, bool ADD2, bool SPLITK>
__global__ __launch_bounds__(256) void tgemm_kernel(
    const float* __restrict__ A, const float* __restrict__ B,
    const float* __restrict__ B2, const float* __restrict__ bias,
    float* __restrict__ C, int M, int N, int K,
    long long sA, long long sB, long long sC) {
    int bz = blockIdx.z;
    int kbeg, kend;
    if (SPLITK) {
        kbeg = bz * (int)sA; kend = kbeg + (int)sA;
        C += bz * sC;
    } else {
        kbeg = 0; kend = K;
        A += bz * sA; B += bz * sB; C += bz * sC;
        if (ADD2) B2 += bz * sB;
    }

    __shared__ uint32_t As[2][16][136];
    __shared__ uint32_t Bs[2][16][136];

    const int tid = threadIdx.x;
    const int lane = tid & 31, warp = tid >> 5;
    const int g = lane >> 2, tig = lane & 3;
    const int wm = (warp >> 2) * 64, wn = (warp & 3) * 32;
    const int m0 = blockIdx.y * 128, n0 = blockIdx.x * 128;

    // load index maps
    const int am = tid >> 2, akq = (tid & 3) * 4;      // A / BT rows
    const int bk = tid >> 5, bnq = (tid & 31) * 4;     // B NN

    float acc[4][4][4];
#pragma unroll
    for (int i = 0; i < 4; i++)
#pragma unroll
        for (int j = 0; j < 4; j++)
#pragma unroll
            for (int l = 0; l < 4; l++) acc[i][j][l] = 0.f;

    float4 ar[2], br[2];
    const float4 zero4 = make_float4(0.f, 0.f, 0.f, 0.f);

    auto loadRegs = [&](int kt) {
        int kk = kbeg + kt * 16;
#pragma unroll
        for (int i = 0; i < 2; i++) {
            int m = am + 64 * i;
            ar[i] = (m0 + m < M)
                        ? *(const float4*)&A[(long long)(m0 + m) * K + kk + akq]
                        : zero4;
        }
        if (BT) {
#pragma unroll
            for (int i = 0; i < 2; i++) {
                int n = am + 64 * i;
                br[i] = (n0 + n < N)
                            ? *(const float4*)&B[(long long)(n0 + n) * K + kk + akq]
                            : zero4;
            }
        } else {
#pragma unroll
            for (int i = 0; i < 2; i++) {
                int k = bk + 8 * i;
                long long o = (long long)(kk + k) * N + n0 + bnq;
                float4 v = *(const float4*)&B[o];
                if (ADD2) {
                    float4 w = *(const float4*)&B2[o];
                    v.x += w.x; v.y += w.y; v.z += w.z; v.w += w.w;
                }
                br[i] = v;
            }
        }
    };
    auto storeSmem = [&](int buf) {
#pragma unroll
        for (int i = 0; i < 2; i++) {
            int m = am + 64 * i;
            float v[4] = {ar[i].x, ar[i].y, ar[i].z, ar[i].w};
#pragma unroll
            for (int j = 0; j < 4; j++) As[buf][akq + j][m] = f2tf(v[j]);
        }
        if (BT) {
#pragma unroll
            for (int i = 0; i < 2; i++) {
                int n = am + 64 * i;
                float v[4] = {br[i].x, br[i].y, br[i].z, br[i].w};
#pragma unroll
                for (int j = 0; j < 4; j++) Bs[buf][akq + j][n] = f2tf(v[j]);
            }
        } else {
#pragma unroll
            for (int i = 0; i < 2; i++) {
                int k = bk + 8 * i;
                float v[4] = {br[i].x, br[i].y, br[i].z, br[i].w};
#pragma unroll
                for (int j = 0; j < 4; j++) Bs[buf][k][bnq + j] = f2tf(v[j]);
            }
        }
    };
    auto compute = [&](int buf) {
#pragma unroll
        for (int ks = 0; ks < 2; ks++) {
            int k = ks * 8;
            uint32_t af[4][4], bf[4][2];
#pragma unroll
            for (int mt = 0; mt < 4; mt++) {
                int r = wm + mt * 16 + g;
                af[mt][0] = As[buf][k + tig][r];
                af[mt][1] = As[buf][k + tig][r + 8];
                af[mt][2] = As[buf][k + tig + 4][r];
                af[mt][3] = As[buf][k + tig + 4][r + 8];
            }
#pragma unroll
            for (int nt = 0; nt < 4; nt++) {
                int c = wn + nt * 8 + g;
                bf[nt][0] = Bs[buf][k + tig][c];
                bf[nt][1] = Bs[buf][k + tig + 4][c];
            }
#pragma unroll
            for (int mt = 0; mt < 4; mt++)
#pragma unroll
                for (int nt = 0; nt < 4; nt++) mma_tf32(acc[mt][nt], af[mt], bf[nt]);
        }
    };

    int ktiles = (kend - kbeg) / 16;
    loadRegs(0);
    storeSmem(0);
    __syncthreads();
    int cur = 0;
    for (int kt = 0; kt < ktiles; kt++) {
        if (kt + 1 < ktiles) loadRegs(kt + 1);
        compute(cur);
        if (kt + 1 < ktiles) {
            storeSmem(cur ^ 1);
            __syncthreads();
            cur ^= 1;
        }
    }

    // epilogue
#pragma unroll
    for (int mt = 0; mt < 4; mt++) {
#pragma unroll
        for (int nt = 0; nt < 4; nt++) {
            int m = m0 + wm + mt * 16 + g;
            int n = n0 + wn + nt * 8 + 2 * tig;
            float* a4 = acc[mt][nt];
            if (SPLITK) {
                if (m < M) *(float2*)&C[(long long)m * N + n] = make_float2(a4[0], a4[1]);
                if (m + 8 < M) *(float2*)&C[(long long)(m + 8) * N + n] = make_float2(a4[2], a4[3]);
            } else {
                float bn0 = 0.f, bn1 = 0.f;
                if (BIAS_N && bias) { bn0 = bias[n]; bn1 = bias[n + 1]; }
                if (m < M) {
                    float bm = (!BIAS_N && bias) ? bias[m] : 0.f;
                    float v0 = a4[0] + bm + bn0, v1 = a4[1] + bm + bn1;
                    if (RELU) { v0 = fmaxf(v0, 0.f); v1 = fmaxf(v1, 0.f); }
                    *(float2*)&C[(long long)m * N + n] = make_float2(v0, v1);
                }
                if (m + 8 < M) {
                    float bm = (!BIAS_N && bias) ? bias[m + 8] : 0.f;
                    float v0 = a4[2] + bm + bn0, v1 = a4[3] + bm + bn1;
                    if (RELU) { v0 = fmaxf(v0, 0.f); v1 = fmaxf(v1, 0.f); }
                    *(float2*)&C[(long long)(m + 8) * N + n] = make_float2(v0, v1);
                }
            }
        }
    }
}

// ---------------- window attention ----------------
__global__ __launch_bounds__(128) void attn_kernel() {
    int win = blockIdx.x, h = blockIdx.y;
    int b = win >> 10;
    int wl = win & 1023;
    int wy = wl >> 5, wx = wl & 31;
    int y0 = wy * 8, x0 = wx * 8;
    __shared__ float qs[NTOK][HD + 1];
    __shared__ float ks[NTOK][HD + 1];
    __shared__ float vs[NTOK][HD + 1];
    __shared__ float at[NTOK][NTOK + 1];
    int tid = threadIdx.x;
    const float scale = 0.25f;
    const float* Qb = g_QK + ((long long)b * 2 * CC + h * HD) * HW;
    const float* Kb = g_QK + ((long long)b * 2 * CC + CC + h * HD) * HW;
    const float* Vb = g_V + ((long long)b * CC + h * HD) * HW;
    for (int idx = tid; idx < NTOK * HD; idx += 128) {
        int ix = idx & 7, iy = (idx >> 3) & 7, d = idx >> 6;
        long long off = (long long)d * HW + (y0 + iy) * WWID + x0 + ix;
        int t = iy * 8 + ix;
        qs[t][d] = Qb[off] * scale;
        ks[t][d] = Kb[off];
        vs[t][d] = Vb[off];
    }
    __syncthreads();
    {
        int m = tid & 63;
        float kreg[HD];
#pragma unroll
        for (int d = 0; d < HD; d++) kreg[d] = ks[m][d];
        for (int i = 0; i < 32; i++) {
            int n = (i * 128 + tid) >> 6;
            float s = 0.f;
#pragma unroll
            for (int d = 0; d < HD; d++) s += qs[n][d] * kreg[d];
            at[n][m] = s + g_bias[(h * NTOK + n) * NTOK + m];
        }
    }
    __syncthreads();
    if (tid < NTOK) {
        int n = tid;
        float mx = -1e30f;
        for (int j = 0; j < NTOK; j++) mx = fmaxf(mx, at[n][j]);
        float sum = 0.f;
        for (int j = 0; j < NTOK; j++) { float e = expf(at[n][j] - mx); at[n][j] = e; sum += e; }
        float inv = 1.f / sum;
        for (int j = 0; j < NTOK; j++) at[n][j] *= inv;
    }
    __syncthreads();
    {
        int d = tid & 15;
        int gg = tid >> 4;
        float acc[8];
#pragma unroll
        for (int j = 0; j < 8; j++) acc[j] = 0.f;
        for (int mm = 0; mm < NTOK; mm++) {
            float v = vs[mm][d];
#pragma unroll
            for (int j = 0; j < 8; j++) acc[j] += at[gg + j * 8][mm] * v;
        }
        float* awp = g_aw + (long long)win * NC + h * HD + d;
#pragma unroll
        for (int j = 0; j < 8; j++) awp[(gg + j * 8) * CC] = acc[j];
    }
}

// ---------------- src stats ----------------
__global__ __launch_bounds__(256) void stats_src_kernel() {
    int b = blockIdx.y;
    const float* p = g_aw + (long long)b * NWIN * NC;
    long long n = (long long)NWIN * NC;
    double s = 0.0, s2 = 0.0;
    for (long long i = (long long)blockIdx.x * blockDim.x + threadIdx.x; i < n;
         i += (long long)gridDim.x * blockDim.x) {
        double v = p[i];
        s += v; s2 += v * v;
    }
    __shared__ double sh[256], sh2[256];
    sh[threadIdx.x] = s; sh2[threadIdx.x] = s2;
    __syncthreads();
    for (int st = 128; st > 0; st >>= 1) {
        if (threadIdx.x < st) { sh[threadIdx.x] += sh[threadIdx.x + st]; sh2[threadIdx.x] += sh2[threadIdx.x + st]; }
        __syncthreads();
    }
    if (threadIdx.x == 0) { atomicAdd(&g_acc[b][0], sh[0]); atomicAdd(&g_acc[b][1], sh2[0]); }
}

// ---------------- emb: sum split-K partials + bias + relu, layer2, l2norm ----------------
__global__ __launch_bounds__(256) void emb2_kernel(const float* __restrict__ w2,
                                                   const float* __restrict__ b2,
                                                   const float* __restrict__ b1) {
    int w = blockIdx.x;
    __shared__ float h[HIDDEN];
    __shared__ float e[PD];
    __shared__ float nrm;
    int tid = threadIdx.x;
    float a = b1[tid];
#pragma unroll
    for (int p = 0; p < KSPLIT; p++)
        a += g_hidden[(size_t)p * BWIN * HIDDEN + (size_t)w * HIDDEN + tid];
    h[tid] = fmaxf(a, 0.f);
    __syncthreads();
    if (tid < PD) {
        float acc = b2[tid];
        const float* wr = w2 + tid * HIDDEN;
        for (int j = 0; j < HIDDEN; j++) acc += wr[j] * h[j];
        e[tid] = acc;
    }
    __syncthreads();
    if (tid == 0) {
        float s = 0.f;
        for (int i = 0; i < PD; i++) s += e[i] * e[i];
        nrm = 1.f / (sqrtf(s) + 1e-8f);
    }
    __syncthreads();
    if (tid < PD) g_emb[w * PD + tid] = e[tid] * nrm;
}

// ---------------- finalize stats ----------------
__global__ __launch_bounds__(256) void stats2_kernel() {
    int b = blockIdx.x;
    const float* p = g_emb + b * NWIN * PD;
    int n = NWIN * PD;
    double s = 0.0, s2 = 0.0;
    for (int i = threadIdx.x; i < n; i += 256) { double v = p[i]; s += v; s2 += v * v; }
    __shared__ double sh[256], sh2[256];
    sh[threadIdx.x] = s; sh2[threadIdx.x] = s2;
    __syncthreads();
    for (int st = 128; st > 0; st >>= 1) {
        if (threadIdx.x < st) { sh[threadIdx.x] += sh[threadIdx.x + st]; sh2[threadIdx.x] += sh2[threadIdx.x + st]; }
        __syncthreads();
    }
    if (threadIdx.x == 0) {
        double mean = sh[0] / n;
        double var = sh2[0] / n - mean * mean;
        g_stats[b][2] = (float)mean;
        g_stats[b][3] = (float)sqrt(var + 1e-8);
        double cnt = (double)NWIN * NC;
        double sm = g_acc[b][0] / cnt;
        double sv = g_acc[b][1] / cnt - sm * sm;
        g_stats[b][0] = (float)sm;
        g_stats[b][1] = (float)sqrt(sv + 1e-8);
    }
}

// ---------------- global attention weights ----------------
__global__ __launch_bounds__(256) void attg_kernel(const float* __restrict__ alpha,
                                                   const float* __restrict__ beta) {
    int b = blockIdx.y, n = blockIdx.x;
    __shared__ float en[PD];
    __shared__ float row[NWIN];
    __shared__ float red[256];
    int tid = threadIdx.x;
    if (tid < PD) en[tid] = g_emb[(b * NWIN + n) * PD + tid];
    __syncthreads();
    float al = 30.f * alpha[0], be = 20.f * beta[0];
    float ls = 0.f;
    for (int m = tid; m < NWIN; m += 256) {
        const float* em = g_emb + (b * NWIN + m) * PD;
        float s = 0.f;
#pragma unroll
        for (int d = 0; d < PD; d++) s += en[d] * em[d];
        float v = expf(al * s + be);
        row[m] = v; ls += v;
    }
    red[tid] = ls;
    __syncthreads();
    for (int st = 128; st > 0; st >>= 1) {
        if (tid < st) red[tid] += red[tid + st];
        __syncthreads();
    }
    float inv = 1.f / (red[0] + 1e-8f);
    float* outp = g_attg + ((long long)b * NWIN + n) * NWIN;
    for (int m = tid; m < NWIN; m += 256) outp[m] = row[m] * inv;
}

// ---------------- renormalize rw + window reverse ----------------
__global__ __launch_bounds__(256) void norm_rev_kernel() {
    int win = blockIdx.x;
    int b = win >> 10, wl = win & 1023, wy = wl >> 5, wx = wl & 31;
    __shared__ float s[CC * 65];
    int tid = threadIdx.x;
    float cm = g_stats[b][2], cs = g_stats[b][3], sm0 = g_stats[b][0], ss = g_stats[b][1];
    float sc = ss / cs;
    float off = sm0 - cm * sc;
    const float* p = g_rw + (long long)win * NC;
    for (int i = tid; i < NC; i += 256) {
        int n = i / CC, c = i - n * CC;
        s[c * 65 + n] = p[i] * sc + off;
    }
    __syncthreads();
    float* outp = g_attn_out + (long long)b * CC * HW + (wy * 8) * WWID + wx * 8;
    for (int t = tid; t < CC * 8; t += 256) {
        int c = t >> 3, iy = t & 7;
        float* o = outp + (long long)c * HW + iy * WWID;
        const float* sr = &s[c * 65];
#pragma unroll
        for (int ix = 0; ix < 8; ix++) o[ix] = sr[iy * 8 + ix];
    }
}

// ---------------- depthwise 5x5 conv (reflect pad) ----------------
__global__ __launch_bounds__(256) void dwconv_kernel(const float* __restrict__ dw_w,
                                                     const float* __restrict__ dw_b) {
    int bc = blockIdx.z;
    int c = bc % CC;
    __shared__ float wgt[25];
    if (threadIdx.y == 0 && threadIdx.x < 25) wgt[threadIdx.x] = dw_w[c * 25 + threadIdx.x];
    __syncthreads();
    int x = blockIdx.x * 32 + threadIdx.x;
    int y = blockIdx.y * 8 + threadIdx.y;
    const float* vp = g_V + (long long)bc * HW;
    float acc = dw_b[c];
#pragma unroll
    for (int ky = 0; ky < 5; ky++) {
        int yy = y + ky - 2;
        yy = yy < 0 ? -yy : (yy > 255 ? 510 - yy : yy);
#pragma unroll
        for (int kx = 0; kx < 5; kx++) {
            int xx = x + kx - 2;
            xx = xx < 0 ? -xx : (xx > 255 ? 510 - xx : xx);
            acc += wgt[ky * 5 + kx] * vp[yy * WWID + xx];
        }
    }
    g_conv[(long long)bc * HW + y * WWID + x] = acc;
}

// ---------------- launch ----------------
extern "C" void kernel_launch(void* const* d_in, const int* in_sizes, int n_in,
                              void* d_out, int out_size) {
    (void)in_sizes; (void)n_in; (void)out_size;
    const float* X        = (const float*)d_in[0];
    const float* V_w      = (const float*)d_in[1];
    const float* V_b      = (const float*)d_in[2];
    const float* QK_w     = (const float*)d_in[3];
    const float* QK_b     = (const float*)d_in[4];
    const float* proj_w   = (const float*)d_in[5];
    const float* proj_b   = (const float*)d_in[6];
    const float* dw_w     = (const float*)d_in[7];
    const float* dw_b     = (const float*)d_in[8];
    const float* meta_w1  = (const float*)d_in[9];
    const float* meta_b1  = (const float*)d_in[10];
    const float* meta_w2  = (const float*)d_in[11];
    const float* meta_b2  = (const float*)d_in[12];
    const float* pe_w1    = (const float*)d_in[13];
    const float* pe_b1    = (const float*)d_in[14];
    const float* pe_w2    = (const float*)d_in[15];
    const float* pe_b2    = (const float*)d_in[16];
    const float* att_alpha = (const float*)d_in[17];
    const float* att_beta  = (const float*)d_in[18];
    float* out = (float*)d_out;

    float *pV, *pQK, *paw, *phid, *pattg, *prw, *pao, *pconv;
    cudaGetSymbolAddress((void**)&pV, g_V);
    cudaGetSymbolAddress((void**)&pQK, g_QK);
    cudaGetSymbolAddress((void**)&paw, g_aw);
    cudaGetSymbolAddress((void**)&phid, g_hidden);
    cudaGetSymbolAddress((void**)&pattg, g_attg);
    cudaGetSymbolAddress((void**)&prw, g_rw);
    cudaGetSymbolAddress((void**)&pao, g_attn_out);
    cudaGetSymbolAddress((void**)&pconv, g_conv);

    zero_acc_kernel<<<1, 32>>>();
    bias_kernel<<<64, 64>>>(meta_w1, meta_b1, meta_w2, meta_b2);

    // QK = QK_w @ X  (M=192, N=65536, K=96) per batch
    tgemm_kernel<false, false, false, false, false><<<dim3(512, 2, BATCH), 256>>>(
        QK_w, X, nullptr, QK_b, pQK, 2 * CC, HW, CC,
        0LL, (long long)CC * HW, (long long)2 * CC * HW);
    // V = V_w @ X
    tgemm_kernel<false, false, false, false, false><<<dim3(512, 1, BATCH), 256>>>(
        V_w, X, nullptr, V_b, pV, CC, HW, CC,
        0LL, (long long)CC * HW, (long long)CC * HW);

    attn_kernel<<<dim3(BWIN, NHEADS), 128>>>();
    stats_src_kernel<<<dim3(64, BATCH), 256>>>();

    // hidden partials = aw @ pe_w1^T  (M=4096, N=256, K=6144), split-K=4
    tgemm_kernel<true, false, false, false, true><<<dim3(2, 32, KSPLIT), 256>>>(
        paw, pe_w1, nullptr, nullptr, phid, BWIN, HIDDEN, NC,
        (long long)(NC / KSPLIT), 0LL, (long long)BWIN * HIDDEN);
    emb2_kernel<<<BWIN, 256>>>(pe_w2, pe_b2, pe_b1);
    stats2_kernel<<<BATCH, 256>>>();
    attg_kernel<<<dim3(NWIN, BATCH), 256>>>(att_alpha, att_beta);

    // rw = att_g @ aw  (M=1024, N=6144, K=1024) per batch
    tgemm_kernel<false, false, false, false, false><<<dim3(48, 8, BATCH), 256>>>(
        pattg, paw, nullptr, nullptr, prw, NWIN, NC, NWIN,
        (long long)NWIN * NWIN, (long long)NWIN * NC, (long long)NWIN * NC);

    norm_rev_kernel<<<BWIN, 256>>>();
    dwconv_kernel<<<dim3(8, 32, BATCH * CC), dim3(32, 8)>>>(dw_w, dw_b);

    // out = proj_w @ (conv + attn_out) + proj_b  (M=96, N=65536, K=96) per batch
    tgemm_kernel<false, false, false, true, false><<<dim3(512, 1, BATCH), 256>>>(
        proj_w, pconv, pao, proj_b, out, CC, HW, CC,
        0LL, (long long)CC * HW, (long long)CC * HW);
}

// round 3
// speedup vs baseline: 2.9495x; 1.3181x over previous
#include <cuda_runtime.h>
#include <math.h>
#include <stdint.h>

#define CC 96
#define HW 65536
#define BATCH 4
#define NTOK 64
#define NHEADS 6
#define HD 16
#define NWIN 1024
#define BWIN 4096
#define NC 6144
#define HIDDEN 256
#define PD 30
#define KSPLIT 4

// ---------------- scratch ----------------
__device__ float g_QKV[(size_t)BATCH * HW * 288];   // NHWC fused Q|K|V
__device__ float g_aw[(size_t)BWIN * NC];           // [win][tok][96]
__device__ float g_hidden[(size_t)KSPLIT * BWIN * HIDDEN];
__device__ float g_emb[BWIN * PD];
__device__ float g_attg[(size_t)BATCH * NWIN * NWIN];
__device__ float g_rw[(size_t)BWIN * NC];
__device__ float g_conv[(size_t)BATCH * HW * CC];   // NHWC dwconv out
__device__ float g_bias[NHEADS * NTOK * NTOK];
__device__ float g_w[288 * 96];                     // packed QKV weights [n][k]
__device__ float g_wb[288];
__device__ float g_dww[25 * 96];                    // dw weights transposed [tap][c]
__device__ float2 g_part[BWIN * NHEADS];            // per-(win,head) sum/sumsq
__device__ double g_acc[BATCH][2];
__device__ float g_stats[BATCH][4];

// ---------------- pack weights ----------------
__global__ void pack_kernel(const float* __restrict__ QK_w, const float* __restrict__ QK_b,
                            const float* __restrict__ V_w, const float* __restrict__ V_b,
                            const float* __restrict__ dw_w) {
    int i = blockIdx.x * 256 + threadIdx.x;
    if (i < 288 * 96) {
        int n = i / 96, k = i - n * 96;
        g_w[i] = (n < 192) ? QK_w[n * 96 + k] : V_w[(n - 192) * 96 + k];
    }
    if (i < 288) g_wb[i] = (i < 192) ? QK_b[i] : V_b[i - 192];
    if (i < 2400) {
        int t = i / 96, c = i - t * 96;
        g_dww[i] = dw_w[c * 25 + t];
    }
}

// ---------------- rel-pos bias MLP ----------------
__global__ void bias_kernel(const float* __restrict__ w1, const float* __restrict__ b1,
                            const float* __restrict__ w2, const float* __restrict__ b2) {
    int n = blockIdx.x, m = threadIdx.x;
    float d0 = (float)((n >> 3) - (m >> 3));
    float d1 = (float)((n & 7) - (m & 7));
    float r0 = copysignf(log1pf(fabsf(d0)), d0);
    float r1 = copysignf(log1pf(fabsf(d1)), d1);
    float out[NHEADS];
#pragma unroll
    for (int h = 0; h < NHEADS; h++) out[h] = b2[h];
    for (int k = 0; k < 256; k++) {
        float hv = fmaxf(w1[2 * k] * r0 + w1[2 * k + 1] * r1 + b1[k], 0.f);
#pragma unroll
        for (int h = 0; h < NHEADS; h++) out[h] += w2[h * 256 + k] * hv;
    }
#pragma unroll
    for (int h = 0; h < NHEADS; h++) g_bias[(h * NTOK + n) * NTOK + m] = out[h];
}

// ---------------- TF32 GEMM, cp.async pipeline, fragment-side cvt ----------------
__device__ __forceinline__ uint32_t f2tf(float f) {
    uint32_t u;
    asm("cvt.rna.tf32.f32 %0, %1;" : "=r"(u) : "f"(f));
    return u;
}
__device__ __forceinline__ void mma_tf32(float d[4], const uint32_t a[4],
                                         const uint32_t b[2]) {
    asm volatile(
        "mma.sync.aligned.m16n8k8.row.col.f32.tf32.tf32.f32 "
        "{%0,%1,%2,%3}, {%4,%5,%6,%7}, {%8,%9}, {%0,%1,%2,%3};\n"
        : "+f"(d[0]), "+f"(d[1]), "+f"(d[2]), "+f"(d[3])
        : "r"(a[0]), "r"(a[1]), "r"(a[2]), "r"(a[3]), "r"(b[0]), "r"(b[1]));
}
__device__ __forceinline__ void cpa16(uint32_t dst, const float* src, bool p) {
    int sz = p ? 16 : 0;
    asm volatile("cp.async.cg.shared.global [%0], [%1], 16, %2;\n" ::"r"(dst),
                 "l"(src), "r"(sz));
}

// AM: 0 = A row-major [M][K]; 1 = A k-major [K][lda] (take column slice m0..)
// BM: 0 = B NN [K][N]; 1 = B BT [N][K]
// FUSE: proj-style: B operand = conv[n][k] + renorm(window-mapped rw)
template <int AM, int BM, bool BIAS_N, bool RELU, bool SPLITK, bool FUSE>
__global__ __launch_bounds__(256) void tgemm(
    const float* __restrict__ A, const float* __restrict__ B,
    const float* __restrict__ bias, float* __restrict__ C, int M, int N, int K,
    long long lda, long long sA, long long sB, long long sC,
    const float* __restrict__ RW) {
    const int bz = blockIdx.z;
    int kbeg, kend;
    float sc = 0.f, off = 0.f;
    if (SPLITK) {
        kbeg = bz * (int)sA; kend = kbeg + (int)sA;
        C += bz * sC;
    } else {
        kbeg = 0; kend = K;
        A += bz * sA; B += bz * sB; C += bz * sC;
        if (FUSE) {
            float cm = g_stats[bz][2], cs = g_stats[bz][3];
            float sm = g_stats[bz][0], ss = g_stats[bz][1];
            sc = ss / cs; off = sm - cm * sc;
        }
    }

    __shared__ float As[2][2560];
    __shared__ float Bs[2][2560];
    const uint32_t asb = (uint32_t)__cvta_generic_to_shared(&As[0][0]);
    const uint32_t bsb = (uint32_t)__cvta_generic_to_shared(&Bs[0][0]);

    const int tid = threadIdx.x;
    const int lane = tid & 31, warp = tid >> 5;
    const int g = lane >> 2, tig = lane & 3;
    const int wm = (warp >> 2) * 64, wn = (warp & 3) * 32;
    const int m0 = blockIdx.y * 128, n0 = blockIdx.x * 128;

    float acc[4][4][4];
#pragma unroll
    for (int i = 0; i < 4; i++)
#pragma unroll
        for (int j = 0; j < 4; j++)
#pragma unroll
            for (int l = 0; l < 4; l++) acc[i][j][l] = 0.f;

    auto loadStage = [&](int st, int kt) {
        int kk = kbeg + kt * 16;
        uint32_t ab = asb + st * 10240;
        uint32_t bb = bsb + st * 10240;
        // ---- A ----
#pragma unroll
        for (int i = 0; i < 2; i++) {
            int idx = tid + i * 256;
            if (AM == 0) {
                int m = idx >> 2, kq = (idx & 3) * 4;
                bool p = (m0 + m < M);
                cpa16(ab + (m * 20 + kq) * 4,
                      A + (long long)(m0 + m) * K + kk + kq, p);
            } else {
                int k = idx >> 5, mq = (idx & 31) * 4;
                cpa16(ab + (k * 136 + mq) * 4,
                      A + (long long)(kk + k) * lda + m0 + mq, true);
            }
        }
        // ---- B ----
#pragma unroll
        for (int i = 0; i < 2; i++) {
            int idx = tid + i * 256;
            if (FUSE) {
                int n = idx >> 2, kq = (idx & 3) * 4;
                int p = n0 + n;
                float4 cv = *(const float4*)&B[(size_t)p * 96 + kk + kq];
                int y = p >> 8, x = p & 255;
                int win = (y >> 3) * 32 + (x >> 3);
                int tok = ((y & 7) << 3) + (x & 7);
                const float4 rv = *(const float4*)&RW[(((size_t)(bz * 1024 + win) * 64 + tok) * 96 + kk + kq)];
                float4 v;
                v.x = cv.x + rv.x * sc + off;
                v.y = cv.y + rv.y * sc + off;
                v.z = cv.z + rv.z * sc + off;
                v.w = cv.w + rv.w * sc + off;
                *(float4*)&Bs[st][n * 20 + kq] = v;
            } else if (BM == 0) {
                int k = idx >> 5, nq = (idx & 31) * 4;
                cpa16(bb + (k * 136 + nq) * 4,
                      B + (long long)(kk + k) * N + n0 + nq, true);
            } else {
                int n = idx >> 2, kq = (idx & 3) * 4;
                bool p = (n0 + n < N);
                cpa16(bb + (n * 20 + kq) * 4,
                      B + (long long)(n0 + n) * K + kk + kq, p);
            }
        }
    };

    auto compute = [&](int st) {
        const float* Ab = &As[st][0];
        const float* Bb = &Bs[st][0];
#pragma unroll
        for (int ks = 0; ks < 2; ks++) {
            int k = ks * 8;
            uint32_t af[4][4], bf[4][2];
#pragma unroll
            for (int mt = 0; mt < 4; mt++) {
                int r = wm + mt * 16 + g;
                if (AM == 0) {
                    af[mt][0] = f2tf(Ab[r * 20 + k + tig]);
                    af[mt][1] = f2tf(Ab[(r + 8) * 20 + k + tig]);
                    af[mt][2] = f2tf(Ab[r * 20 + k + tig + 4]);
                    af[mt][3] = f2tf(Ab[(r + 8) * 20 + k + tig + 4]);
                } else {
                    af[mt][0] = f2tf(Ab[(k + tig) * 136 + r]);
                    af[mt][1] = f2tf(Ab[(k + tig) * 136 + r + 8]);
                    af[mt][2] = f2tf(Ab[(k + tig + 4) * 136 + r]);
                    af[mt][3] = f2tf(Ab[(k + tig + 4) * 136 + r + 8]);
                }
            }
#pragma unroll
            for (int nt = 0; nt < 4; nt++) {
                int c = wn + nt * 8 + g;
                if (BM == 0 && !FUSE) {
                    bf[nt][0] = f2tf(Bb[(k + tig) * 136 + c]);
                    bf[nt][1] = f2tf(Bb[(k + tig + 4) * 136 + c]);
                } else {
                    bf[nt][0] = f2tf(Bb[c * 20 + k + tig]);
                    bf[nt][1] = f2tf(Bb[c * 20 + k + tig + 4]);
                }
            }
#pragma unroll
            for (int mt = 0; mt < 4; mt++)
#pragma unroll
                for (int nt = 0; nt < 4; nt++) mma_tf32(acc[mt][nt], af[mt], bf[nt]);
        }
    };

    const int ktiles = (kend - kbeg) / 16;
    loadStage(0, 0);
    asm volatile("cp.async.commit_group;\n");
    int cur = 0;
    for (int kt = 0; kt < ktiles; kt++) {
        if (kt + 1 < ktiles) loadStage(cur ^ 1, kt + 1);
        asm volatile("cp.async.commit_group;\n");
        if (kt + 1 < ktiles) {
            asm volatile("cp.async.wait_group 1;\n");
        } else {
            asm volatile("cp.async.wait_group 0;\n");
        }
        __syncthreads();
        compute(cur);
        __syncthreads();
        cur ^= 1;
    }

#pragma unroll
    for (int mt = 0; mt < 4; mt++) {
#pragma unroll
        for (int nt = 0; nt < 4; nt++) {
            int m = m0 + wm + mt * 16 + g;
            int n = n0 + wn + nt * 8 + 2 * tig;
            float* a4 = acc[mt][nt];
            if (n >= N) continue;
            if (SPLITK) {
                if (m < M) *(float2*)&C[(long long)m * N + n] = make_float2(a4[0], a4[1]);
                if (m + 8 < M) *(float2*)&C[(long long)(m + 8) * N + n] = make_float2(a4[2], a4[3]);
            } else {
                float bn0 = 0.f, bn1 = 0.f;
                if (BIAS_N && bias) { bn0 = bias[n]; bn1 = (n + 1 < N) ? bias[n + 1] : 0.f; }
                if (m < M) {
                    float bm = (!BIAS_N && bias) ? bias[m] : 0.f;
                    float v0 = a4[0] + bm + bn0, v1 = a4[1] + bm + bn1;
                    if (RELU) { v0 = fmaxf(v0, 0.f); v1 = fmaxf(v1, 0.f); }
                    *(float2*)&C[(long long)m * N + n] = make_float2(v0, v1);
                }
                if (m + 8 < M) {
                    float bm = (!BIAS_N && bias) ? bias[m + 8] : 0.f;
                    float v0 = a4[2] + bm + bn0, v1 = a4[3] + bm + bn1;
                    if (RELU) { v0 = fmaxf(v0, 0.f); v1 = fmaxf(v1, 0.f); }
                    *(float2*)&C[(long long)(m + 8) * N + n] = make_float2(v0, v1);
                }
            }
        }
    }
}

// ---------------- window attention (NHWC) + partial stats ----------------
__global__ __launch_bounds__(128) void attn_kernel() {
    int win = blockIdx.x, h = blockIdx.y;
    int b = win >> 10, wl = win & 1023, wy = wl >> 5, wx = wl & 31;
    int y0 = wy * 8, x0 = wx * 8;
    __shared__ float qs[64][17], ks[64][17], vs[64][17];
    __shared__ float at[64][65];
    __shared__ float rs[128], rs2[128];
    int tid = threadIdx.x;
    const size_t base = (size_t)b * HW * 288;
#pragma unroll
    for (int i = 0; i < 6; i++) {
        int idx = tid + i * 128;
        int mat = idx >> 8, rem = idx & 255;
        int t = rem >> 2, q = (rem & 3) * 4;
        int p = (y0 + (t >> 3)) * 256 + x0 + (t & 7);
        float4 v = *(const float4*)&g_QKV[base + (size_t)p * 288 + mat * 96 + h * 16 + q];
        float s = (mat == 0) ? 0.25f : 1.f;
        float* dst = (mat == 0) ? &qs[t][q] : (mat == 1) ? &ks[t][q] : &vs[t][q];
        dst[0] = v.x * s; dst[1] = v.y * s; dst[2] = v.z * s; dst[3] = v.w * s;
    }
    __syncthreads();
    {
        int m = tid & 63;
        float kreg[HD];
#pragma unroll
        for (int d = 0; d < HD; d++) kreg[d] = ks[m][d];
        for (int i = 0; i < 32; i++) {
            int n = (i * 128 + tid) >> 6;
            float s = 0.f;
#pragma unroll
            for (int d = 0; d < HD; d++) s += qs[n][d] * kreg[d];
            at[n][m] = s + g_bias[(h * NTOK + n) * NTOK + m];
        }
    }
    __syncthreads();
    if (tid < NTOK) {
        int n = tid;
        float mx = -1e30f;
        for (int j = 0; j < NTOK; j++) mx = fmaxf(mx, at[n][j]);
        float sum = 0.f;
        for (int j = 0; j < NTOK; j++) { float e = expf(at[n][j] - mx); at[n][j] = e; sum += e; }
        float inv = 1.f / sum;
        for (int j = 0; j < NTOK; j++) at[n][j] *= inv;
    }
    __syncthreads();
    {
        int d = tid & 15;
        int gg = tid >> 4;
        float acc[8];
#pragma unroll
        for (int j = 0; j < 8; j++) acc[j] = 0.f;
        for (int mm = 0; mm < NTOK; mm++) {
            float v = vs[mm][d];
#pragma unroll
            for (int j = 0; j < 8; j++) acc[j] += at[gg + j * 8][mm] * v;
        }
        float* awp = g_aw + (size_t)win * NC + h * HD + d;
        float s = 0.f, s2 = 0.f;
#pragma unroll
        for (int j = 0; j < 8; j++) {
            awp[(gg + j * 8) * CC] = acc[j];
            s += acc[j]; s2 += acc[j] * acc[j];
        }
        rs[tid] = s; rs2[tid] = s2;
    }
    __syncthreads();
    for (int st = 64; st > 0; st >>= 1) {
        if (tid < st) { rs[tid] += rs[tid + st]; rs2[tid] += rs2[tid + st]; }
        __syncthreads();
    }
    if (tid == 0) g_part[win * NHEADS + h] = make_float2(rs[0], rs2[0]);
}

// ---------------- reduce partials -> src stats ----------------
__global__ __launch_bounds__(256) void part_reduce_kernel() {
    int b = blockIdx.x;
    double s = 0.0, s2 = 0.0;
    for (int i = threadIdx.x; i < NWIN * NHEADS; i += 256) {
        float2 v = g_part[b * NWIN * NHEADS + i];
        s += v.x; s2 += v.y;
    }
    __shared__ double sh[256], sh2[256];
    sh[threadIdx.x] = s; sh2[threadIdx.x] = s2;
    __syncthreads();
    for (int st = 128; st > 0; st >>= 1) {
        if (threadIdx.x < st) { sh[threadIdx.x] += sh[threadIdx.x + st]; sh2[threadIdx.x] += sh2[threadIdx.x + st]; }
        __syncthreads();
    }
    if (threadIdx.x == 0) { g_acc[b][0] = sh[0]; g_acc[b][1] = sh2[0]; }
}

// ---------------- emb: sum split-K + bias + relu, layer2, l2norm ----------------
__global__ __launch_bounds__(256) void emb2_kernel(const float* __restrict__ w2,
                                                   const float* __restrict__ b2,
                                                   const float* __restrict__ b1) {
    int w = blockIdx.x;
    __shared__ float h[HIDDEN];
    __shared__ float e[PD];
    __shared__ float nrm;
    int tid = threadIdx.x;
    float a = b1[tid];
#pragma unroll
    for (int p = 0; p < KSPLIT; p++)
        a += g_hidden[(size_t)p * BWIN * HIDDEN + (size_t)w * HIDDEN + tid];
    h[tid] = fmaxf(a, 0.f);
    __syncthreads();
    if (tid < PD) {
        float acc = b2[tid];
        const float* wr = w2 + tid * HIDDEN;
        for (int j = 0; j < HIDDEN; j++) acc += wr[j] * h[j];
        e[tid] = acc;
    }
    __syncthreads();
    if (tid == 0) {
        float s = 0.f;
        for (int i = 0; i < PD; i++) s += e[i] * e[i];
        nrm = 1.f / (sqrtf(s) + 1e-8f);
    }
    __syncthreads();
    if (tid < PD) g_emb[w * PD + tid] = e[tid] * nrm;
}

// ---------------- finalize stats ----------------
__global__ __launch_bounds__(256) void stats2_kernel() {
    int b = blockIdx.x;
    const float* p = g_emb + b * NWIN * PD;
    int n = NWIN * PD;
    double s = 0.0, s2 = 0.0;
    for (int i = threadIdx.x; i < n; i += 256) { double v = p[i]; s += v; s2 += v * v; }
    __shared__ double sh[256], sh2[256];
    sh[threadIdx.x] = s; sh2[threadIdx.x] = s2;
    __syncthreads();
    for (int st = 128; st > 0; st >>= 1) {
        if (threadIdx.x < st) { sh[threadIdx.x] += sh[threadIdx.x + st]; sh2[threadIdx.x] += sh2[threadIdx.x + st]; }
        __syncthreads();
    }
    if (threadIdx.x == 0) {
        double mean = sh[0] / n;
        double var = sh2[0] / n - mean * mean;
        g_stats[b][2] = (float)mean;
        g_stats[b][3] = (float)sqrt(var + 1e-8);
        double cnt = (double)NWIN * NC;
        double sm = g_acc[b][0] / cnt;
        double sv = g_acc[b][1] / cnt - sm * sm;
        g_stats[b][0] = (float)sm;
        g_stats[b][1] = (float)sqrt(sv + 1e-8);
    }
}

// ---------------- global attention weights ----------------
__global__ __launch_bounds__(256) void attg_kernel(const float* __restrict__ alpha,
                                                   const float* __restrict__ beta) {
    int b = blockIdx.y, n = blockIdx.x;
    __shared__ float en[PD];
    __shared__ float row[NWIN];
    __shared__ float red[256];
    int tid = threadIdx.x;
    if (tid < PD) en[tid] = g_emb[(b * NWIN + n) * PD + tid];
    __syncthreads();
    float al = 30.f * alpha[0], be = 20.f * beta[0];
    float ls = 0.f;
    for (int m = tid; m < NWIN; m += 256) {
        const float* em = g_emb + (b * NWIN + m) * PD;
        float s = 0.f;
#pragma unroll
        for (int d = 0; d < PD; d++) s += en[d] * em[d];
        float v = expf(al * s + be);
        row[m] = v; ls += v;
    }
    red[tid] = ls;
    __syncthreads();
    for (int st = 128; st > 0; st >>= 1) {
        if (tid < st) red[tid] += red[tid + st];
        __syncthreads();
    }
    float inv = 1.f / (red[0] + 1e-8f);
    float* outp = g_attg + ((size_t)b * NWIN + n) * NWIN;
    for (int m = tid; m < NWIN; m += 256) outp[m] = row[m] * inv;
}

// ---------------- depthwise 5x5 conv, NHWC, register-tiled ----------------
__device__ __forceinline__ int refl(int v) {
    return v < 0 ? -v : (v > 255 ? 510 - v : v);
}
__global__ __launch_bounds__(96) void dwconv_kernel(const float* __restrict__ dw_b) {
    int b = blockIdx.z;
    int tid = threadIdx.x;
    int c4 = tid % 24, xo = tid / 24;
    int c = c4 * 4;
    int x = blockIdx.x * 4 + xo;
    int y0 = blockIdx.y * 4;
    float4 w4[25];
#pragma unroll
    for (int t = 0; t < 25; t++) w4[t] = *(const float4*)&g_dww[t * 96 + c];
    float4 bias = *(const float4*)&dw_b[c];
    float4 acc[4];
#pragma unroll
    for (int j = 0; j < 4; j++) acc[j] = bias;
    const float* vbase = g_QKV + (size_t)b * HW * 288 + 192 + c;
#pragma unroll
    for (int dy = -2; dy <= 5; dy++) {
        int yy = y0 + dy;
        int ry = refl(yy);
#pragma unroll
        for (int dx = -2; dx <= 2; dx++) {
            int rx = refl(x + dx);
            float4 v = *(const float4*)&vbase[(size_t)(ry * 256 + rx) * 288];
#pragma unroll
            for (int j = 0; j < 4; j++) {
                int ky = dy - j;  // yy - (y0+j)
                if (ky >= -2 && ky <= 2) {
                    float4 w = w4[(ky + 2) * 5 + (dx + 2)];
                    acc[j].x += v.x * w.x; acc[j].y += v.y * w.y;
                    acc[j].z += v.z * w.z; acc[j].w += v.w * w.w;
                }
            }
        }
    }
#pragma unroll
    for (int j = 0; j < 4; j++)
        *(float4*)&g_conv[((size_t)b * HW + (size_t)(y0 + j) * 256 + x) * CC + c] = acc[j];
}

// ---------------- launch ----------------
extern "C" void kernel_launch(void* const* d_in, const int* in_sizes, int n_in,
                              void* d_out, int out_size) {
    (void)in_sizes; (void)n_in; (void)out_size;
    const float* X        = (const float*)d_in[0];
    const float* V_w      = (const float*)d_in[1];
    const float* V_b      = (const float*)d_in[2];
    const float* QK_w     = (const float*)d_in[3];
    const float* QK_b     = (const float*)d_in[4];
    const float* proj_w   = (const float*)d_in[5];
    const float* proj_b   = (const float*)d_in[6];
    const float* dw_w     = (const float*)d_in[7];
    const float* dw_b     = (const float*)d_in[8];
    const float* meta_w1  = (const float*)d_in[9];
    const float* meta_b1  = (const float*)d_in[10];
    const float* meta_w2  = (const float*)d_in[11];
    const float* meta_b2  = (const float*)d_in[12];
    const float* pe_w1    = (const float*)d_in[13];
    const float* pe_b1    = (const float*)d_in[14];
    const float* pe_w2    = (const float*)d_in[15];
    const float* pe_b2    = (const float*)d_in[16];
    const float* att_alpha = (const float*)d_in[17];
    const float* att_beta  = (const float*)d_in[18];
    float* out = (float*)d_out;

    float *pQKV, *paw, *phid, *pattg, *prw, *pconv, *pw, *pwb;
    cudaGetSymbolAddress((void**)&pQKV, g_QKV);
    cudaGetSymbolAddress((void**)&paw, g_aw);
    cudaGetSymbolAddress((void**)&phid, g_hidden);
    cudaGetSymbolAddress((void**)&pattg, g_attg);
    cudaGetSymbolAddress((void**)&prw, g_rw);
    cudaGetSymbolAddress((void**)&pconv, g_conv);
    cudaGetSymbolAddress((void**)&pw, g_w);
    cudaGetSymbolAddress((void**)&pwb, g_wb);

    pack_kernel<<<108, 256>>>(QK_w, QK_b, V_w, V_b, dw_w);
    bias_kernel<<<64, 64>>>(meta_w1, meta_b1, meta_w2, meta_b2);

    // QKV NHWC: C[pixel][288] = X^T @ W^T  (M=65536, N=288, K=96) per batch
    tgemm<1, 1, true, false, false, false><<<dim3(3, 512, BATCH), 256>>>(
        X, pw, pwb, pQKV, HW, 288, 96, (long long)HW,
        (long long)96 * HW, 0LL, (long long)HW * 288, nullptr);

    attn_kernel<<<dim3(BWIN, NHEADS), 128>>>();
    part_reduce_kernel<<<BATCH, 256>>>();
    dwconv_kernel<<<dim3(64, 64, BATCH), 96>>>(dw_b);

    // hidden partials = aw @ pe_w1^T (M=4096, N=256, K=6144), split-K=4
    tgemm<0, 1, false, false, true, false><<<dim3(2, 32, KSPLIT), 256>>>(
        paw, pe_w1, nullptr, phid, BWIN, HIDDEN, NC, 0LL,
        (long long)(NC / KSPLIT), 0LL, (long long)BWIN * HIDDEN, nullptr);
    emb2_kernel<<<BWIN, 256>>>(pe_w2, pe_b2, pe_b1);
    stats2_kernel<<<BATCH, 256>>>();
    attg_kernel<<<dim3(NWIN, BATCH), 256>>>(att_alpha, att_beta);

    // rw = att_g @ aw (M=1024, N=6144, K=1024) per batch
    tgemm<0, 0, false, false, false, false><<<dim3(48, 8, BATCH), 256>>>(
        pattg, paw, nullptr, prw, NWIN, NC, NWIN, 0LL,
        (long long)NWIN * NWIN, (long long)NWIN * NC, (long long)NWIN * NC, nullptr);

    // out = proj_w @ (conv + renorm(rw))^T  (M=96, N=65536, K=96), fused epilogue
    tgemm<0, 1, false, false, false, true><<<dim3(512, 1, BATCH), 256>>>(
        proj_w, pconv, proj_b, out, CC, HW, CC, 0LL,
        0LL, (long long)HW * CC, (long long)96 * HW, prw);
}